// round 5
// baseline (speedup 1.0000x reference)
#include <cuda_runtime.h>

#define A_TOTAL 76725
#define NCLS 80
#define KTOP 1000
#define NB 4096
#define CAND 2048
#define IMGF 640.0f

// scratch: decoded boxes (x1,y1,x2,y2) per anchor
__device__ float4 g_boxes4[A_TOTAL];

// -------------------- Kernel 1: decode + clip boxes --------------------
__global__ void decode_kernel(const float* __restrict__ reg,
                              const float* __restrict__ anc) {
    int a = blockIdx.x * blockDim.x + threadIdx.x;
    if (a >= A_TOTAL) return;
    float a0 = anc[a * 4 + 0], a1 = anc[a * 4 + 1];
    float a2 = anc[a * 4 + 2], a3 = anc[a * 4 + 3];
    float aw = a2 - a0, ah = a3 - a1;
    float cx = a0 + 0.5f * aw, cy = a1 + 0.5f * ah;
    float dx = reg[a * 4 + 0] * 0.1f;
    float dy = reg[a * 4 + 1] * 0.1f;
    float dw = reg[a * 4 + 2] * 0.2f;
    float dh = reg[a * 4 + 3] * 0.2f;
    float pcx = cx + dx * aw;
    float pcy = cy + dy * ah;
    float pw = expf(dw) * aw;
    float ph = expf(dh) * ah;
    float4 b;
    b.x = fmaxf(pcx - 0.5f * pw, 0.0f);
    b.y = fmaxf(pcy - 0.5f * ph, 0.0f);
    b.z = fminf(pcx + 0.5f * pw, IMGF);
    b.w = fminf(pcy + 0.5f * ph, IMGF);
    g_boxes4[a] = b;
}

// ---------- Kernel 2: per-class top-K select + sort + NMS + output ----------
// one block (1024 threads) per class
__global__ __launch_bounds__(1024) void topk_nms_kernel(
    const float* __restrict__ cls, float* __restrict__ out) {
    __shared__ unsigned long long s_cand[CAND];  // 16 KB
    __shared__ float s_over[NB];                 // 16 KB: hist (int) then boxes
    __shared__ float s_area[KTOP];               // 4 KB
    __shared__ int s_keep[1024];                 // 4 KB
    __shared__ int s_chunk[128];
    __shared__ int s_misc[2];                    // [0]=threshold bucket, [1]=counter

    int* hist = (int*)s_over;
    float* s_box = s_over;  // reuse after histogram phase is done
    const int tid = threadIdx.x;
    const int c = blockIdx.x;

    // ---- phase 1: histogram over this class's scores ----
    for (int b = tid; b < NB; b += 1024) hist[b] = 0;
    __syncthreads();
    for (int a = tid; a < A_TOTAL; a += 1024) {
        float s = cls[a * NCLS + c];
        int b = (int)(s * (float)NB);
        b = min(max(b, 0), NB - 1);
        atomicAdd(&hist[b], 1);
    }
    __syncthreads();

    // ---- phase 2: find threshold bucket B (smallest B with suffix >= K) ----
    if (tid < 128) {
        int sum = 0;
#pragma unroll
        for (int b = 0; b < 32; b++) sum += hist[tid * 32 + b];
        s_chunk[tid] = sum;
    }
    __syncthreads();
    if (tid == 0) {
        int acc = 0;
        int ch = 127;
        for (; ch > 0; ch--) {
            if (acc + s_chunk[ch] >= KTOP) break;
            acc += s_chunk[ch];
        }
        int B = ch * 32;
        for (int b = ch * 32 + 31; b >= ch * 32; b--) {
            acc += hist[b];
            if (acc >= KTOP) { B = b; break; }
        }
        s_misc[0] = B;
        s_misc[1] = 0;
    }
    __syncthreads();
    const int B = s_misc[0];

    // ---- phase 3: gather candidates (score >= bucket B) ----
    s_cand[tid] = 0ULL;
    s_cand[tid + 1024] = 0ULL;
    __syncthreads();
    for (int a = tid; a < A_TOTAL; a += 1024) {
        float s = cls[a * NCLS + c];
        int b = (int)(s * (float)NB);
        b = min(max(b, 0), NB - 1);
        if (b >= B) {
            int pos = atomicAdd(&s_misc[1], 1);
            if (pos < CAND) {
                unsigned int sb = __float_as_uint(s);
                // composite key: score desc, index asc (lax.top_k tie-break)
                s_cand[pos] = ((unsigned long long)sb << 32) |
                              (unsigned long long)(0xFFFFFFFFu - (unsigned)a);
            }
        }
    }
    __syncthreads();

    // ---- phase 4: bitonic sort CAND keys, descending ----
    for (unsigned k = 2; k <= CAND; k <<= 1) {
        for (unsigned j = k >> 1; j > 0; j >>= 1) {
#pragma unroll
            for (unsigned base = 0; base < CAND; base += 1024) {
                unsigned e = base + tid;
                unsigned ix = e ^ j;
                if (ix > e) {
                    unsigned long long x = s_cand[e];
                    unsigned long long y = s_cand[ix];
                    bool desc = ((e & k) == 0);
                    bool sw = desc ? (x < y) : (x > y);
                    if (sw) { s_cand[e] = y; s_cand[ix] = x; }
                }
            }
            __syncthreads();
        }
    }

    // ---- phase 5: extract top-K, load boxes, init keep ----
    float mx1 = 0.f, my1 = 0.f, mx2 = 0.f, my2 = 0.f;
    float myarea = 0.f, myscore = 0.f;
    bool mykeep = false;
    if (tid < KTOP) {
        unsigned long long key = s_cand[tid];
        myscore = __uint_as_float((unsigned)(key >> 32));
        unsigned idx = 0xFFFFFFFFu - (unsigned)(key & 0xFFFFFFFFu);
        float4 bx = g_boxes4[idx];
        mx1 = bx.x; my1 = bx.y; mx2 = bx.z; my2 = bx.w;
        myarea = (mx2 - mx1) * (my2 - my1);
        mykeep = (myscore > 0.001f);
    }
    __syncthreads();  // all sort/hist reads done before overwriting s_over
    if (tid < KTOP) {
        s_box[tid * 4 + 0] = mx1;
        s_box[tid * 4 + 1] = my1;
        s_box[tid * 4 + 2] = mx2;
        s_box[tid * 4 + 3] = my2;
        s_area[tid] = myarea;
    }
    s_keep[tid] = (tid < KTOP && mykeep) ? 1 : 0;
    __syncthreads();

    // ---- phase 6: sequential greedy NMS ----
    for (int i = 0; i < KTOP - 1; i++) {
        if (s_keep[i]) {
            if (mykeep && tid > i && tid < KTOP) {
                float bx1 = s_box[i * 4 + 0];
                float by1 = s_box[i * 4 + 1];
                float bx2 = s_box[i * 4 + 2];
                float by2 = s_box[i * 4 + 3];
                float lx = fmaxf(mx1, bx1);
                float ly = fmaxf(my1, by1);
                float rx = fminf(mx2, bx2);
                float ry = fminf(my2, by2);
                float w = fmaxf(rx - lx, 0.0f);
                float h = fmaxf(ry - ly, 0.0f);
                float inter = w * h;
                float iou = inter / (s_area[i] + myarea - inter + 1e-8f);
                if (iou > 0.5f) {
                    mykeep = false;
                    s_keep[tid] = 0;
                }
            }
        }
        __syncthreads();
    }

    // ---- phase 7: write outputs ----
    // layout (float32): scores[C*K] | labels[C*K] | boxes[C*K*4] | keep[C*K]
    if (tid < KTOP) {
        float kf = mykeep ? 1.0f : 0.0f;
        int o = c * KTOP + tid;
        const int CK = NCLS * KTOP;  // 80000
        out[o] = myscore * kf;
        out[CK + o] = (float)c;
        out[2 * CK + o * 4 + 0] = mx1 * kf;
        out[2 * CK + o * 4 + 1] = my1 * kf;
        out[2 * CK + o * 4 + 2] = mx2 * kf;
        out[2 * CK + o * 4 + 3] = my2 * kf;
        out[6 * CK + o] = kf;
    }
}

extern "C" void kernel_launch(void* const* d_in, const int* in_sizes, int n_in,
                              void* d_out, int out_size) {
    // inputs: img_batch [1,3,640,640], cls_output [1,A,80],
    //         reg_output [1,A,4], anchors [1,A,4]  (all float32)
    const float* cls = (const float*)d_in[1];
    const float* reg = (const float*)d_in[2];
    const float* anc = (const float*)d_in[3];
    float* out = (float*)d_out;

    decode_kernel<<<(A_TOTAL + 255) / 256, 256>>>(reg, anc);
    topk_nms_kernel<<<NCLS, 1024>>>(cls, out);
}